// round 1
// baseline (speedup 1.0000x reference)
#include <cuda_runtime.h>
#include <math.h>

#define Bn   16384
#define HIDn 4096
#define HDn  256

// ---------------- scratch (static device allocation is allowed) ----------------
__device__ float g_H0[Bn * HDn];   // h @ W0[:4096] + b0, computed once
__device__ float g_X[Bn * 16];     // current SE(3) state, row-major 4x4 per row

// ---------------- scalar math helpers ----------------
__device__ __forceinline__ float gelu_f(float x) {
    return 0.5f * x * (1.0f + erff(x * 0.70710678118654752f));
}
__device__ __forceinline__ float sigmoid_f(float x) {
    return 1.0f / (1.0f + expf(-x));
}

__device__ __forceinline__ void exp_se3_dev(const float* xi, float* X) {
    float wx = xi[0], wy = xi[1], wz = xi[2];
    float vx = xi[3], vy = xi[4], vz = xi[5];
    float th2 = wx * wx + wy * wy + wz * wz + 1e-20f;
    float th  = sqrtf(th2);
    bool small = th < 1e-3f;
    float ths = small ? 1.0f : th;
    float s = sinf(ths), c = cosf(ths);
    float A  = small ? (1.0f - th2 / 6.0f)            : (s / ths);
    float Bc = small ? (0.5f - th2 / 24.0f)           : ((1.0f - c) / (ths * ths));
    float Cc = small ? (1.0f / 6.0f - th2 / 120.0f)   : ((ths - s) / (ths * ths * ths));
    float wx2 = wx * wx, wy2 = wy * wy, wz2 = wz * wz;
    float xy = wx * wy, xz = wx * wz, yz = wy * wz;
    float R00 = 1.0f - Bc * (wy2 + wz2), R01 = -A * wz + Bc * xy, R02 =  A * wy + Bc * xz;
    float R10 =  A * wz + Bc * xy, R11 = 1.0f - Bc * (wx2 + wz2), R12 = -A * wx + Bc * yz;
    float R20 = -A * wy + Bc * xz, R21 =  A * wx + Bc * yz, R22 = 1.0f - Bc * (wx2 + wy2);
    float V00 = 1.0f - Cc * (wy2 + wz2), V01 = -Bc * wz + Cc * xy, V02 =  Bc * wy + Cc * xz;
    float V10 =  Bc * wz + Cc * xy, V11 = 1.0f - Cc * (wx2 + wz2), V12 = -Bc * wx + Cc * yz;
    float V20 = -Bc * wy + Cc * xz, V21 =  Bc * wx + Cc * yz, V22 = 1.0f - Cc * (wx2 + wy2);
    float tx = V00 * vx + V01 * vy + V02 * vz;
    float ty = V10 * vx + V11 * vy + V12 * vz;
    float tz = V20 * vx + V21 * vy + V22 * vz;
    X[0] = R00; X[1] = R01; X[2]  = R02; X[3]  = tx;
    X[4] = R10; X[5] = R11; X[6]  = R12; X[7]  = ty;
    X[8] = R20; X[9] = R21; X[10] = R22; X[11] = tz;
    X[12] = 0.0f; X[13] = 0.0f; X[14] = 0.0f; X[15] = 1.0f;
}

__device__ __forceinline__ void log_se3_dev(const float* X, float* xi) {
    float R00 = X[0], R01 = X[1], R02 = X[2],  px = X[3];
    float R10 = X[4], R11 = X[5], R12 = X[6],  py = X[7];
    float R20 = X[8], R21 = X[9], R22 = X[10], pz = X[11];
    float tr = R00 + R11 + R22;
    float cc = fminf(fmaxf((tr - 1.0f) * 0.5f, -1.0f + 1e-7f), 1.0f - 1e-7f);
    float th = acosf(cc);
    bool small = th < 1e-3f;
    float ths = small ? 1.0f : th;
    float sn = sinf(ths), csn = cosf(ths);
    float fac = small ? (0.5f + th * th / 12.0f) : (ths / (2.0f * sn));
    float wx = fac * (R21 - R12);
    float wy = fac * (R02 - R20);
    float wz = fac * (R10 - R01);
    float D = small ? (1.0f / 12.0f)
                    : ((1.0f - ths * sn / (2.0f * (1.0f - csn))) / (ths * ths));
    float wx2 = wx * wx, wy2 = wy * wy, wz2 = wz * wz;
    float xy = wx * wy, xz = wx * wz, yz = wy * wz;
    // Vinv = I - 0.5*W + D*W^2
    float V00 = 1.0f - D * (wy2 + wz2), V01 =  0.5f * wz + D * xy, V02 = -0.5f * wy + D * xz;
    float V10 = -0.5f * wz + D * xy, V11 = 1.0f - D * (wx2 + wz2), V12 =  0.5f * wx + D * yz;
    float V20 =  0.5f * wy + D * xz, V21 = -0.5f * wx + D * yz, V22 = 1.0f - D * (wx2 + wy2);
    xi[0] = wx; xi[1] = wy; xi[2] = wz;
    xi[3] = V00 * px + V01 * py + V02 * pz;
    xi[4] = V10 * px + V11 * py + V12 * pz;
    xi[5] = V20 * px + V21 * py + V22 * pz;
}

// ---------------- init: X0 = exp_se3(0.1 * xi0) ----------------
__global__ void init_kernel(const float* __restrict__ xi0) {
    int r = blockIdx.x * blockDim.x + threadIdx.x;
    if (r >= Bn) return;
    float xi[6];
#pragma unroll
    for (int j = 0; j < 6; j++) xi[j] = 0.1f * xi0[r * 6 + j];
    float X[16];
    exp_se3_dev(xi, X);
#pragma unroll
    for (int j = 0; j < 16; j++) g_X[(size_t)r * 16 + j] = X[j];
}

// ---------------- H0 = h @ W0[:4096,:] + b0  (16384 x 4096 x 256) ----------------
__global__ void __launch_bounds__(256) gemm_h0_kernel(
    const float* __restrict__ h, const float* __restrict__ W0, const float* __restrict__ b0) {
    __shared__ __align__(16) float As[16][68];   // [k][m], padded
    __shared__ __align__(16) float Bs[16][256];  // [k][n]
    int brow = blockIdx.x * 64;
    int tid = threadIdx.x;
    int tm = tid >> 5;   // warp id -> 8 rows
    int tn = tid & 31;   // lane -> 8 cols
    float acc[8][8];
#pragma unroll
    for (int i = 0; i < 8; i++)
#pragma unroll
        for (int j = 0; j < 8; j++) acc[i][j] = 0.0f;

    int ar = tid >> 2;
    int ak = (tid & 3) * 4;
    for (int k0 = 0; k0 < HIDn; k0 += 16) {
        float4 av = *(const float4*)(h + (size_t)(brow + ar) * HIDn + k0 + ak);
        As[ak + 0][ar] = av.x; As[ak + 1][ar] = av.y;
        As[ak + 2][ar] = av.z; As[ak + 3][ar] = av.w;
#pragma unroll
        for (int q = 0; q < 4; q++) {
            int f = tid + q * 256;
            int row = f >> 6, col = (f & 63) * 4;
            *(float4*)&Bs[row][col] = *(const float4*)(W0 + (size_t)(k0 + row) * HDn + col);
        }
        __syncthreads();
#pragma unroll
        for (int kk = 0; kk < 16; kk++) {
            float a[8], b[8];
            *(float4*)&a[0] = *(float4*)&As[kk][tm * 8];
            *(float4*)&a[4] = *(float4*)&As[kk][tm * 8 + 4];
            *(float4*)&b[0] = *(float4*)&Bs[kk][tn * 8];
            *(float4*)&b[4] = *(float4*)&Bs[kk][tn * 8 + 4];
#pragma unroll
            for (int i = 0; i < 8; i++)
#pragma unroll
                for (int j = 0; j < 8; j++) acc[i][j] += a[i] * b[j];
        }
        __syncthreads();
    }
#pragma unroll
    for (int i = 0; i < 8; i++) {
        int r = brow + tm * 8 + i;
#pragma unroll
        for (int j = 0; j < 8; j++) {
            int c = tn * 8 + j;
            g_H0[(size_t)r * HDn + c] = acc[i][j] + b0[c];
        }
    }
}

// ---------------- gripper = sigmoid(gelu(h @ gW1 + gb1) @ gW2 + gb2) ----------------
__global__ void __launch_bounds__(256) gripper_kernel(
    const float* __restrict__ h, const float* __restrict__ gW1,
    const float* __restrict__ gb1, const float* __restrict__ gW2,
    const float* __restrict__ gb2, float* __restrict__ out) {
    __shared__ __align__(16) float As[32][68];
    __shared__ __align__(16) float Bs[32][64];
    __shared__ float sred[64][16];
    int brow = blockIdx.x * 64;
    int tid = threadIdx.x;
    int tm = tid >> 4;   // 0..15 -> 4 rows each
    int tn = tid & 15;   // 0..15 -> 4 cols each
    float acc[4][4];
#pragma unroll
    for (int i = 0; i < 4; i++)
#pragma unroll
        for (int j = 0; j < 4; j++) acc[i][j] = 0.0f;

    for (int k0 = 0; k0 < HIDn; k0 += 32) {
#pragma unroll
        for (int q = 0; q < 2; q++) {
            int f = tid + q * 256;
            int row = f >> 3, kc = (f & 7) * 4;
            float4 av = *(const float4*)(h + (size_t)(brow + row) * HIDn + k0 + kc);
            As[kc + 0][row] = av.x; As[kc + 1][row] = av.y;
            As[kc + 2][row] = av.z; As[kc + 3][row] = av.w;
        }
#pragma unroll
        for (int q = 0; q < 2; q++) {
            int f = tid + q * 256;
            int row = f >> 4, col = (f & 15) * 4;
            *(float4*)&Bs[row][col] = *(const float4*)(gW1 + (size_t)(k0 + row) * 64 + col);
        }
        __syncthreads();
#pragma unroll
        for (int kk = 0; kk < 32; kk++) {
            float a[4], b[4];
            *(float4*)&a[0] = *(float4*)&As[kk][tm * 4];
            *(float4*)&b[0] = *(float4*)&Bs[kk][tn * 4];
#pragma unroll
            for (int i = 0; i < 4; i++)
#pragma unroll
                for (int j = 0; j < 4; j++) acc[i][j] += a[i] * b[j];
        }
        __syncthreads();
    }
#pragma unroll
    for (int i = 0; i < 4; i++) {
        float p = 0.0f;
#pragma unroll
        for (int j = 0; j < 4; j++) {
            int c = tn * 4 + j;
            p += gelu_f(acc[i][j] + gb1[c]) * gW2[c];
        }
        sred[tm * 4 + i][tn] = p;
    }
    __syncthreads();
    if (tid < 64) {
        float s = 0.0f;
#pragma unroll
        for (int t = 0; t < 16; t++) s += sred[tid][t];
        out[(size_t)Bn * 16 + brow + tid] = sigmoid_f(s + gb2[0]);
    }
}

// ---------------- layernorm over 256 cols, 8 warps x 8 rows ----------------
__device__ __forceinline__ void block_ln(float* ys, const float* __restrict__ g,
                                         const float* __restrict__ be, int wid, int lane) {
    float gv[8], bv[8];
#pragma unroll
    for (int j = 0; j < 8; j++) { gv[j] = g[lane + j * 32]; bv[j] = be[lane + j * 32]; }
#pragma unroll
    for (int rr = 0; rr < 8; rr++) {
        int r = wid * 8 + rr;
        float v[8]; float s = 0.0f, s2 = 0.0f;
#pragma unroll
        for (int j = 0; j < 8; j++) {
            v[j] = ys[r * HDn + lane + j * 32];
            s += v[j]; s2 += v[j] * v[j];
        }
#pragma unroll
        for (int o = 16; o > 0; o >>= 1) {
            s  += __shfl_xor_sync(0xffffffffu, s,  o);
            s2 += __shfl_xor_sync(0xffffffffu, s2, o);
        }
        float m   = s * (1.0f / HDn);
        float var = s2 * (1.0f / HDn) - m * m;
        float rv  = rsqrtf(var + 1e-5f);
#pragma unroll
        for (int j = 0; j < 8; j++)
            ys[r * HDn + lane + j * 32] = (v[j] - m) * rv * gv[j] + bv[j];
    }
}

// ---------------- one ODE step, fully fused; block = 64 rows ----------------
__global__ void __launch_bounds__(256) step_kernel(
    const float* __restrict__ W0,  const float* __restrict__ g0,
    const float* __restrict__ be0, const float* __restrict__ Wr,
    const float* __restrict__ br,  const float* __restrict__ gr,
    const float* __restrict__ ber, const float* __restrict__ Wout,
    const float* __restrict__ bout, const int* __restrict__ n_steps_p, int step) {
    extern __shared__ float smem_pool[];
    float* ys   = smem_pool;            // 64*256
    float* wt   = ys + 64 * HDn;        // 16*256
    float* Xs   = wt + 16 * HDn;        // 64*16
    float* xis  = Xs + 64 * 16;         // 64*6
    float* temb = xis + 64 * 6;         // 64

    int ns = *n_steps_p;
    if (step >= ns) return;
    float dt = 1.0f / (float)ns;
    float tval = (float)step * dt;

    int tid = threadIdx.x;
    int brow = blockIdx.x * 64;
    int wid = tid >> 5, lane = tid & 31;

    // phase 0: temb + per-row log_se3 (threads 0..63)
    if (tid < 64) {
        int j = tid & 31;
        float freq = expf(-(float)j * (logf(10000.0f) / 31.0f));
        float e = tval * freq;
        temb[tid] = (tid < 32) ? sinf(e) : cosf(e);
        float X[16];
#pragma unroll
        for (int q = 0; q < 16; q++) {
            X[q] = g_X[(size_t)(brow + tid) * 16 + q];
            Xs[tid * 16 + q] = X[q];
        }
        float xi[6];
        log_se3_dev(X, xi);
#pragma unroll
        for (int q = 0; q < 6; q++) xis[tid * 6 + q] = xi[q];
    }
    __syncthreads();

    // phase 1: input layer; thread owns column c = tid for all 64 rows
    {
        float tc = 0.0f;
#pragma unroll 8
        for (int d = 0; d < 64; d++)
            tc += temb[d] * W0[(size_t)(4102 + d) * HDn + tid];
        float w0xi[6];
#pragma unroll
        for (int j = 0; j < 6; j++) w0xi[j] = W0[(size_t)(4096 + j) * HDn + tid];
        for (int r = 0; r < 64; r++) {
            float v = g_H0[(size_t)(brow + r) * HDn + tid] + tc;
#pragma unroll
            for (int j = 0; j < 6; j++) v += xis[r * 6 + j] * w0xi[j];
            ys[r * HDn + tid] = gelu_f(v);
        }
    }
    __syncthreads();
    block_ln(ys, g0, be0, wid, lane);
    __syncthreads();

    // phase 2: 3 fused hidden layers (64x256 @ 256x256)
    for (int l = 0; l < 3; l++) {
        const float* Wl = Wr + (size_t)l * HDn * HDn;
        float acc[8][8];
#pragma unroll
        for (int i = 0; i < 8; i++)
#pragma unroll
            for (int j = 0; j < 8; j++) acc[i][j] = 0.0f;
        int tm = wid, tn = lane;
        for (int k0 = 0; k0 < HDn; k0 += 16) {
#pragma unroll
            for (int q = 0; q < 4; q++) {
                int f = tid + q * 256;
                int row = f >> 6, col = (f & 63) * 4;
                *(float4*)&wt[row * HDn + col] =
                    *(const float4*)(Wl + (size_t)(k0 + row) * HDn + col);
            }
            __syncthreads();
#pragma unroll
            for (int kk = 0; kk < 16; kk++) {
                float b[8];
                *(float4*)&b[0] = *(float4*)&wt[kk * HDn + tn * 8];
                *(float4*)&b[4] = *(float4*)&wt[kk * HDn + tn * 8 + 4];
#pragma unroll
                for (int i = 0; i < 8; i++) {
                    float a = ys[(tm * 8 + i) * HDn + k0 + kk];
#pragma unroll
                    for (int j = 0; j < 8; j++) acc[i][j] += a * b[j];
                }
            }
            __syncthreads();
        }
        // epilogue: gelu(acc + br) back into ys, then LN
        float brv[8];
#pragma unroll
        for (int j = 0; j < 8; j++) brv[j] = br[l * HDn + tn * 8 + j];
#pragma unroll
        for (int i = 0; i < 8; i++)
#pragma unroll
            for (int j = 0; j < 8; j++)
                ys[(tm * 8 + i) * HDn + tn * 8 + j] = gelu_f(acc[i][j] + brv[j]);
        __syncthreads();
        block_ln(ys, gr + l * HDn, ber + l * HDn, wid, lane);
        __syncthreads();
    }

    // phase 3: v = y @ Wout + bout ; X = X @ exp_se3(dt*v)
    for (int rr = 0; rr < 8; rr++) {
        int r = wid * 8 + rr;
        float p[6] = {0, 0, 0, 0, 0, 0};
        for (int c = lane; c < HDn; c += 32) {
            float yv = ys[r * HDn + c];
#pragma unroll
            for (int j = 0; j < 6; j++) p[j] += yv * Wout[c * 6 + j];
        }
#pragma unroll
        for (int j = 0; j < 6; j++)
#pragma unroll
            for (int o = 16; o > 0; o >>= 1)
                p[j] += __shfl_xor_sync(0xffffffffu, p[j], o);
        if (lane == 0) {
            float xi[6];
#pragma unroll
            for (int j = 0; j < 6; j++) xi[j] = dt * (p[j] + bout[j]);
            float M[16];
            exp_se3_dev(xi, M);
            const float* Xo = &Xs[r * 16];
            float Xn[16];
#pragma unroll
            for (int i = 0; i < 4; i++)
#pragma unroll
                for (int j = 0; j < 4; j++) {
                    float s = 0.0f;
#pragma unroll
                    for (int k = 0; k < 4; k++) s += Xo[i * 4 + k] * M[k * 4 + j];
                    Xn[i * 4 + j] = s;
                }
#pragma unroll
            for (int q = 0; q < 16; q++) g_X[(size_t)(brow + r) * 16 + q] = Xn[q];
        }
    }
}

// ---------------- final copy of X into d_out ----------------
__global__ void copy_x_kernel(float* __restrict__ out) {
    int i = blockIdx.x * blockDim.x + threadIdx.x;
    if (i < Bn * 16) out[i] = g_X[i];
}

// ---------------- launch ----------------
extern "C" void kernel_launch(void* const* d_in, const int* in_sizes, int n_in,
                              void* d_out, int out_size) {
    const float* h    = (const float*)d_in[0];
    const float* xi0  = (const float*)d_in[1];
    const float* W0   = (const float*)d_in[2];
    const float* b0   = (const float*)d_in[3];
    const float* g0   = (const float*)d_in[4];
    const float* be0  = (const float*)d_in[5];
    const float* Wr   = (const float*)d_in[6];
    const float* br   = (const float*)d_in[7];
    const float* gr   = (const float*)d_in[8];
    const float* ber  = (const float*)d_in[9];
    const float* Wout = (const float*)d_in[10];
    const float* bout = (const float*)d_in[11];
    const float* gW1  = (const float*)d_in[12];
    const float* gb1  = (const float*)d_in[13];
    const float* gW2  = (const float*)d_in[14];
    const float* gb2  = (const float*)d_in[15];
    const int*   nst  = (const int*)d_in[16];
    float* out = (float*)d_out;

    const int STEP_SMEM = (64 * 256 + 16 * 256 + 64 * 16 + 64 * 6 + 64) * 4;  // 87808 B
    cudaFuncSetAttribute(step_kernel, cudaFuncAttributeMaxDynamicSharedMemorySize, STEP_SMEM);

    init_kernel<<<Bn / 256, 256>>>(xi0);
    gemm_h0_kernel<<<Bn / 64, 256>>>(h, W0, b0);
    gripper_kernel<<<Bn / 64, 256>>>(h, gW1, gb1, gW2, gb2, out);
    for (int s = 0; s < 10; s++)
        step_kernel<<<Bn / 64, 256, STEP_SMEM>>>(W0, g0, be0, Wr, br, gr, ber,
                                                 Wout, bout, nst, s);
    copy_x_kernel<<<(Bn * 16) / 256, 256>>>(out);
}

// round 2
// speedup vs baseline: 2.1807x; 2.1807x over previous
#include <cuda_runtime.h>
#include <math.h>
#include <stdint.h>

#define Bn   16384
#define HIDn 4096
#define HDn  256

// ---------------- scratch ----------------
__device__ float g_H0[Bn * HDn];   // h @ W0[:4096] + b0, computed once
__device__ float g_X[Bn * 16];     // current SE(3) state, row-major 4x4 per row

// ---------------- scalar math helpers ----------------
__device__ __forceinline__ float gelu_f(float x) {
    return 0.5f * x * (1.0f + erff(x * 0.70710678118654752f));
}
__device__ __forceinline__ float sigmoid_f(float x) {
    return 1.0f / (1.0f + expf(-x));
}
__device__ __forceinline__ uint32_t f2tf32(float x) {
    uint32_t r;
    asm("cvt.rna.tf32.f32 %0, %1;" : "=r"(r) : "f"(x));
    return r;
}
// D += A(16x8) * B(8x8), tf32 inputs, f32 accum
__device__ __forceinline__ void mma_tf32(float* c, uint32_t a0, uint32_t a1,
                                         uint32_t a2, uint32_t a3,
                                         uint32_t b0, uint32_t b1) {
    asm volatile(
        "mma.sync.aligned.m16n8k8.row.col.f32.tf32.tf32.f32 "
        "{%0,%1,%2,%3}, {%4,%5,%6,%7}, {%8,%9}, {%0,%1,%2,%3};"
        : "+f"(c[0]), "+f"(c[1]), "+f"(c[2]), "+f"(c[3])
        : "r"(a0), "r"(a1), "r"(a2), "r"(a3), "r"(b0), "r"(b1));
}

__device__ __forceinline__ void exp_se3_dev(const float* xi, float* X) {
    float wx = xi[0], wy = xi[1], wz = xi[2];
    float vx = xi[3], vy = xi[4], vz = xi[5];
    float th2 = wx * wx + wy * wy + wz * wz + 1e-20f;
    float th  = sqrtf(th2);
    bool small = th < 1e-3f;
    float ths = small ? 1.0f : th;
    float s = sinf(ths), c = cosf(ths);
    float A  = small ? (1.0f - th2 / 6.0f)            : (s / ths);
    float Bc = small ? (0.5f - th2 / 24.0f)           : ((1.0f - c) / (ths * ths));
    float Cc = small ? (1.0f / 6.0f - th2 / 120.0f)   : ((ths - s) / (ths * ths * ths));
    float wx2 = wx * wx, wy2 = wy * wy, wz2 = wz * wz;
    float xy = wx * wy, xz = wx * wz, yz = wy * wz;
    float R00 = 1.0f - Bc * (wy2 + wz2), R01 = -A * wz + Bc * xy, R02 =  A * wy + Bc * xz;
    float R10 =  A * wz + Bc * xy, R11 = 1.0f - Bc * (wx2 + wz2), R12 = -A * wx + Bc * yz;
    float R20 = -A * wy + Bc * xz, R21 =  A * wx + Bc * yz, R22 = 1.0f - Bc * (wx2 + wy2);
    float V00 = 1.0f - Cc * (wy2 + wz2), V01 = -Bc * wz + Cc * xy, V02 =  Bc * wy + Cc * xz;
    float V10 =  Bc * wz + Cc * xy, V11 = 1.0f - Cc * (wx2 + wz2), V12 = -Bc * wx + Cc * yz;
    float V20 = -Bc * wy + Cc * xz, V21 =  Bc * wx + Cc * yz, V22 = 1.0f - Cc * (wx2 + wy2);
    float tx = V00 * vx + V01 * vy + V02 * vz;
    float ty = V10 * vx + V11 * vy + V12 * vz;
    float tz = V20 * vx + V21 * vy + V22 * vz;
    X[0] = R00; X[1] = R01; X[2]  = R02; X[3]  = tx;
    X[4] = R10; X[5] = R11; X[6]  = R12; X[7]  = ty;
    X[8] = R20; X[9] = R21; X[10] = R22; X[11] = tz;
    X[12] = 0.0f; X[13] = 0.0f; X[14] = 0.0f; X[15] = 1.0f;
}

__device__ __forceinline__ void log_se3_dev(const float* X, float* xi) {
    float R00 = X[0], R01 = X[1], R02 = X[2],  px = X[3];
    float R10 = X[4], R11 = X[5], R12 = X[6],  py = X[7];
    float R20 = X[8], R21 = X[9], R22 = X[10], pz = X[11];
    float tr = R00 + R11 + R22;
    float cc = fminf(fmaxf((tr - 1.0f) * 0.5f, -1.0f + 1e-7f), 1.0f - 1e-7f);
    float th = acosf(cc);
    bool small = th < 1e-3f;
    float ths = small ? 1.0f : th;
    float sn = sinf(ths), csn = cosf(ths);
    float fac = small ? (0.5f + th * th / 12.0f) : (ths / (2.0f * sn));
    float wx = fac * (R21 - R12);
    float wy = fac * (R02 - R20);
    float wz = fac * (R10 - R01);
    float D = small ? (1.0f / 12.0f)
                    : ((1.0f - ths * sn / (2.0f * (1.0f - csn))) / (ths * ths));
    float wx2 = wx * wx, wy2 = wy * wy, wz2 = wz * wz;
    float xy = wx * wy, xz = wx * wz, yz = wy * wz;
    float V00 = 1.0f - D * (wy2 + wz2), V01 =  0.5f * wz + D * xy, V02 = -0.5f * wy + D * xz;
    float V10 = -0.5f * wz + D * xy, V11 = 1.0f - D * (wx2 + wz2), V12 =  0.5f * wx + D * yz;
    float V20 =  0.5f * wy + D * xz, V21 = -0.5f * wx + D * yz, V22 = 1.0f - D * (wx2 + wy2);
    xi[0] = wx; xi[1] = wy; xi[2] = wz;
    xi[3] = V00 * px + V01 * py + V02 * pz;
    xi[4] = V10 * px + V11 * py + V12 * pz;
    xi[5] = V20 * px + V21 * py + V22 * pz;
}

// ---------------- init: X0 = exp_se3(0.1 * xi0) ----------------
__global__ void init_kernel(const float* __restrict__ xi0) {
    int r = blockIdx.x * blockDim.x + threadIdx.x;
    if (r >= Bn) return;
    float xi[6];
#pragma unroll
    for (int j = 0; j < 6; j++) xi[j] = 0.1f * xi0[r * 6 + j];
    float X[16];
    exp_se3_dev(xi, X);
#pragma unroll
    for (int j = 0; j < 16; j++) g_X[(size_t)r * 16 + j] = X[j];
}

// ---------------- H0 = h @ W0[:4096,:] + b0, tf32 tensor cores ----------------
// block tile 128(M) x 128(N); 8 warps, warp tile 32x64; k-tile 32
#define AP 36   // As row pad (words): 144B rows -> conflict-free frags + aligned uint4
#define BP 136  // Bs row pad: 544B rows
__global__ void __launch_bounds__(256) gemm_h0_kernel(
    const float* __restrict__ h, const float* __restrict__ W0, const float* __restrict__ b0) {
    __shared__ __align__(16) uint32_t As[128 * AP];
    __shared__ __align__(16) uint32_t Bs[32 * BP];
    int brow = blockIdx.x * 128;
    int n0   = blockIdx.y * 128;
    int tid  = threadIdx.x;
    int wid  = tid >> 5, lane = tid & 31;
    int g = lane >> 2, t = lane & 3;
    int warp_m = (wid >> 1) * 32;
    int warp_n = (wid & 1) * 64;

    float acc[2][8][4];
#pragma unroll
    for (int mf = 0; mf < 2; mf++)
#pragma unroll
        for (int nf = 0; nf < 8; nf++)
#pragma unroll
            for (int q = 0; q < 4; q++) acc[mf][nf][q] = 0.0f;

    for (int k0 = 0; k0 < HIDn; k0 += 32) {
        // stage A 128x32 (pre-converted tf32)
#pragma unroll
        for (int q = 0; q < 4; q++) {
            int f = tid + q * 256;
            int row = f >> 3, c4 = (f & 7) * 4;
            float4 v = *(const float4*)(h + (size_t)(brow + row) * HIDn + k0 + c4);
            uint4 u = make_uint4(f2tf32(v.x), f2tf32(v.y), f2tf32(v.z), f2tf32(v.w));
            *(uint4*)&As[row * AP + c4] = u;
        }
        // stage B 32x128
#pragma unroll
        for (int q = 0; q < 4; q++) {
            int f = tid + q * 256;
            int row = f >> 5, c4 = (f & 31) * 4;
            float4 v = *(const float4*)(W0 + (size_t)(k0 + row) * HDn + n0 + c4);
            uint4 u = make_uint4(f2tf32(v.x), f2tf32(v.y), f2tf32(v.z), f2tf32(v.w));
            *(uint4*)&Bs[row * BP + c4] = u;
        }
        __syncthreads();
#pragma unroll
        for (int k8 = 0; k8 < 4; k8++) {
            int kb = k8 * 8;
            uint32_t a[2][4];
#pragma unroll
            for (int mf = 0; mf < 2; mf++) {
                int r0 = warp_m + mf * 16 + g;
                a[mf][0] = As[r0 * AP + kb + t];
                a[mf][1] = As[(r0 + 8) * AP + kb + t];
                a[mf][2] = As[r0 * AP + kb + t + 4];
                a[mf][3] = As[(r0 + 8) * AP + kb + t + 4];
            }
#pragma unroll
            for (int nf = 0; nf < 8; nf++) {
                int nn = warp_n + nf * 8 + g;
                uint32_t bb0 = Bs[(kb + t) * BP + nn];
                uint32_t bb1 = Bs[(kb + t + 4) * BP + nn];
                mma_tf32(acc[0][nf], a[0][0], a[0][1], a[0][2], a[0][3], bb0, bb1);
                mma_tf32(acc[1][nf], a[1][0], a[1][1], a[1][2], a[1][3], bb0, bb1);
            }
        }
        __syncthreads();
    }
    // epilogue: + b0, write g_H0
#pragma unroll
    for (int mf = 0; mf < 2; mf++) {
        int r0 = brow + warp_m + mf * 16 + g;
#pragma unroll
        for (int nf = 0; nf < 8; nf++) {
            int c0 = n0 + warp_n + nf * 8 + 2 * t;
            float bb0 = b0[c0], bb1 = b0[c0 + 1];
            *(float2*)&g_H0[(size_t)r0 * HDn + c0] =
                make_float2(acc[mf][nf][0] + bb0, acc[mf][nf][1] + bb1);
            *(float2*)&g_H0[(size_t)(r0 + 8) * HDn + c0] =
                make_float2(acc[mf][nf][2] + bb0, acc[mf][nf][3] + bb1);
        }
    }
}

// ---------------- gripper = sigmoid(gelu(h @ gW1 + gb1) @ gW2 + gb2) ----------------
__global__ void __launch_bounds__(256) gripper_kernel(
    const float* __restrict__ h, const float* __restrict__ gW1,
    const float* __restrict__ gb1, const float* __restrict__ gW2,
    const float* __restrict__ gb2, float* __restrict__ out) {
    __shared__ __align__(16) float As2[32][68];
    __shared__ __align__(16) float Bs2[32][64];
    __shared__ float sred[64][16];
    int brow = blockIdx.x * 64;
    int tid = threadIdx.x;
    int tm = tid >> 4;
    int tn = tid & 15;
    float acc[4][4];
#pragma unroll
    for (int i = 0; i < 4; i++)
#pragma unroll
        for (int j = 0; j < 4; j++) acc[i][j] = 0.0f;

    for (int k0 = 0; k0 < HIDn; k0 += 32) {
#pragma unroll
        for (int q = 0; q < 2; q++) {
            int f = tid + q * 256;
            int row = f >> 3, kc = (f & 7) * 4;
            float4 av = *(const float4*)(h + (size_t)(brow + row) * HIDn + k0 + kc);
            As2[kc + 0][row] = av.x; As2[kc + 1][row] = av.y;
            As2[kc + 2][row] = av.z; As2[kc + 3][row] = av.w;
        }
#pragma unroll
        for (int q = 0; q < 2; q++) {
            int f = tid + q * 256;
            int row = f >> 4, col = (f & 15) * 4;
            *(float4*)&Bs2[row][col] = *(const float4*)(gW1 + (size_t)(k0 + row) * 64 + col);
        }
        __syncthreads();
#pragma unroll
        for (int kk = 0; kk < 32; kk++) {
            float a[4], b[4];
            *(float4*)&a[0] = *(float4*)&As2[kk][tm * 4];
            *(float4*)&b[0] = *(float4*)&Bs2[kk][tn * 4];
#pragma unroll
            for (int i = 0; i < 4; i++)
#pragma unroll
                for (int j = 0; j < 4; j++) acc[i][j] += a[i] * b[j];
        }
        __syncthreads();
    }
#pragma unroll
    for (int i = 0; i < 4; i++) {
        float p = 0.0f;
#pragma unroll
        for (int j = 0; j < 4; j++) {
            int c = tn * 4 + j;
            p += gelu_f(acc[i][j] + gb1[c]) * gW2[c];
        }
        sred[tm * 4 + i][tn] = p;
    }
    __syncthreads();
    if (tid < 64) {
        float s = 0.0f;
#pragma unroll
        for (int t2 = 0; t2 < 16; t2++) s += sred[tid][t2];
        out[(size_t)Bn * 16 + brow + tid] = sigmoid_f(s + gb2[0]);
    }
}

// ---------------- layernorm over 256 cols (ys stride 260), 8 warps x 8 rows ----------------
#define YS 260
#define WTS 264
__device__ __forceinline__ void block_ln(float* ys, const float* __restrict__ g,
                                         const float* __restrict__ be, int wid, int lane) {
    float gv[8], bv[8];
#pragma unroll
    for (int j = 0; j < 8; j++) { gv[j] = g[lane + j * 32]; bv[j] = be[lane + j * 32]; }
#pragma unroll
    for (int rr = 0; rr < 8; rr++) {
        int r = wid * 8 + rr;
        float v[8]; float s = 0.0f, s2 = 0.0f;
#pragma unroll
        for (int j = 0; j < 8; j++) {
            v[j] = ys[r * YS + lane + j * 32];
            s += v[j]; s2 += v[j] * v[j];
        }
#pragma unroll
        for (int o = 16; o > 0; o >>= 1) {
            s  += __shfl_xor_sync(0xffffffffu, s,  o);
            s2 += __shfl_xor_sync(0xffffffffu, s2, o);
        }
        float m   = s * (1.0f / HDn);
        float var = s2 * (1.0f / HDn) - m * m;
        float rv  = rsqrtf(var + 1e-5f);
#pragma unroll
        for (int j = 0; j < 8; j++)
            ys[r * YS + lane + j * 32] = (v[j] - m) * rv * gv[j] + bv[j];
    }
}

// ---------------- one ODE step, fused, tensor-core hidden layers ----------------
// block = 64 rows, 256 threads; warp tile 32x64 (warps 2x4)
__global__ void __launch_bounds__(256) step_kernel(
    const float* __restrict__ W0,  const float* __restrict__ g0,
    const float* __restrict__ be0, const float* __restrict__ Wr,
    const float* __restrict__ br,  const float* __restrict__ gr,
    const float* __restrict__ ber, const float* __restrict__ Wout,
    const float* __restrict__ bout, const int* __restrict__ n_steps_p, int step) {
    extern __shared__ float smem_pool[];
    float*    ys   = smem_pool;                 // 64*260
    uint32_t* wt   = (uint32_t*)(ys + 64 * YS); // 16*264 (tf32)
    float*    Xs   = (float*)(wt + 16 * WTS);   // 64*16
    float*    xis  = Xs + 64 * 16;              // 64*6
    float*    temb = xis + 64 * 6;              // 64

    int ns = *n_steps_p;
    if (step >= ns) return;
    float dt = 1.0f / (float)ns;
    float tval = (float)step * dt;

    int tid = threadIdx.x;
    int brow = blockIdx.x * 64;
    int wid = tid >> 5, lane = tid & 31;
    int g = lane >> 2, t = lane & 3;

    // phase 0: temb + per-row log_se3 (threads 0..63)
    if (tid < 64) {
        int j = tid & 31;
        float freq = expf(-(float)j * (logf(10000.0f) / 31.0f));
        float e = tval * freq;
        temb[tid] = (tid < 32) ? sinf(e) : cosf(e);
        float X[16];
#pragma unroll
        for (int q = 0; q < 16; q++) {
            X[q] = g_X[(size_t)(brow + tid) * 16 + q];
            Xs[tid * 16 + q] = X[q];
        }
        float xi[6];
        log_se3_dev(X, xi);
#pragma unroll
        for (int q = 0; q < 6; q++) xis[tid * 6 + q] = xi[q];
    }
    __syncthreads();

    // phase 1: input layer; thread owns column c = tid for all 64 rows
    {
        float tc = 0.0f;
#pragma unroll 8
        for (int d = 0; d < 64; d++)
            tc += temb[d] * W0[(size_t)(4102 + d) * HDn + tid];
        float w0xi[6];
#pragma unroll
        for (int j = 0; j < 6; j++) w0xi[j] = W0[(size_t)(4096 + j) * HDn + tid];
        for (int r = 0; r < 64; r++) {
            float v = g_H0[(size_t)(brow + r) * HDn + tid] + tc;
#pragma unroll
            for (int j = 0; j < 6; j++) v += xis[r * 6 + j] * w0xi[j];
            ys[r * YS + tid] = gelu_f(v);
        }
    }
    __syncthreads();
    block_ln(ys, g0, be0, wid, lane);
    __syncthreads();

    // phase 2: 3 hidden layers via tf32 mma (64x256 @ 256x256)
    int warp_m = (wid >> 2) * 32;
    int warp_n = (wid & 3) * 64;
    for (int l = 0; l < 3; l++) {
        const float* Wl = Wr + (size_t)l * HDn * HDn;
        float acc[2][8][4];
#pragma unroll
        for (int mf = 0; mf < 2; mf++)
#pragma unroll
            for (int nf = 0; nf < 8; nf++)
#pragma unroll
                for (int q = 0; q < 4; q++) acc[mf][nf][q] = 0.0f;

        for (int k0 = 0; k0 < HDn; k0 += 16) {
            // stage 16x256 weight tile, pre-converted; thread -> column tid
#pragma unroll
            for (int i = 0; i < 16; i++)
                wt[i * WTS + tid] = f2tf32(Wl[(size_t)(k0 + i) * HDn + tid]);
            __syncthreads();
#pragma unroll
            for (int k8 = 0; k8 < 2; k8++) {
                int kb = k8 * 8;
                int kcol = k0 + kb;
                uint32_t a[2][4];
#pragma unroll
                for (int mf = 0; mf < 2; mf++) {
                    int r0 = warp_m + mf * 16 + g;
                    a[mf][0] = f2tf32(ys[r0 * YS + kcol + t]);
                    a[mf][1] = f2tf32(ys[(r0 + 8) * YS + kcol + t]);
                    a[mf][2] = f2tf32(ys[r0 * YS + kcol + t + 4]);
                    a[mf][3] = f2tf32(ys[(r0 + 8) * YS + kcol + t + 4]);
                }
#pragma unroll
                for (int nf = 0; nf < 8; nf++) {
                    int nn = warp_n + nf * 8 + g;
                    uint32_t bb0 = wt[(kb + t) * WTS + nn];
                    uint32_t bb1 = wt[(kb + t + 4) * WTS + nn];
                    mma_tf32(acc[0][nf], a[0][0], a[0][1], a[0][2], a[0][3], bb0, bb1);
                    mma_tf32(acc[1][nf], a[1][0], a[1][1], a[1][2], a[1][3], bb0, bb1);
                }
            }
            __syncthreads();
        }
        // epilogue: gelu(acc + br) back into ys, then LN
#pragma unroll
        for (int nf = 0; nf < 8; nf++) {
            int c0 = warp_n + nf * 8 + 2 * t;
            float bb0 = br[l * HDn + c0], bb1 = br[l * HDn + c0 + 1];
#pragma unroll
            for (int mf = 0; mf < 2; mf++) {
                int r0 = warp_m + mf * 16 + g;
                ys[r0 * YS + c0]           = gelu_f(acc[mf][nf][0] + bb0);
                ys[r0 * YS + c0 + 1]       = gelu_f(acc[mf][nf][1] + bb1);
                ys[(r0 + 8) * YS + c0]     = gelu_f(acc[mf][nf][2] + bb0);
                ys[(r0 + 8) * YS + c0 + 1] = gelu_f(acc[mf][nf][3] + bb1);
            }
        }
        __syncthreads();
        block_ln(ys, gr + l * HDn, ber + l * HDn, wid, lane);
        __syncthreads();
    }

    // phase 3: v = y @ Wout + bout ; X = X @ exp_se3(dt*v)
    for (int rr = 0; rr < 8; rr++) {
        int r = wid * 8 + rr;
        float p[6] = {0, 0, 0, 0, 0, 0};
        for (int c = lane; c < HDn; c += 32) {
            float yv = ys[r * YS + c];
#pragma unroll
            for (int j = 0; j < 6; j++) p[j] += yv * Wout[c * 6 + j];
        }
#pragma unroll
        for (int j = 0; j < 6; j++)
#pragma unroll
            for (int o = 16; o > 0; o >>= 1)
                p[j] += __shfl_xor_sync(0xffffffffu, p[j], o);
        if (lane == 0) {
            float xi[6];
#pragma unroll
            for (int j = 0; j < 6; j++) xi[j] = dt * (p[j] + bout[j]);
            float M[16];
            exp_se3_dev(xi, M);
            const float* Xo = &Xs[r * 16];
            float Xn[16];
#pragma unroll
            for (int i = 0; i < 4; i++)
#pragma unroll
                for (int j = 0; j < 4; j++) {
                    float s = 0.0f;
#pragma unroll
                    for (int k = 0; k < 4; k++) s += Xo[i * 4 + k] * M[k * 4 + j];
                    Xn[i * 4 + j] = s;
                }
#pragma unroll
            for (int q = 0; q < 16; q++) g_X[(size_t)(brow + r) * 16 + q] = Xn[q];
        }
    }
}

// ---------------- final copy of X into d_out ----------------
__global__ void copy_x_kernel(float* __restrict__ out) {
    int i = blockIdx.x * blockDim.x + threadIdx.x;
    if (i < Bn * 16) out[i] = g_X[i];
}

// ---------------- launch ----------------
extern "C" void kernel_launch(void* const* d_in, const int* in_sizes, int n_in,
                              void* d_out, int out_size) {
    const float* h    = (const float*)d_in[0];
    const float* xi0  = (const float*)d_in[1];
    const float* W0   = (const float*)d_in[2];
    const float* b0   = (const float*)d_in[3];
    const float* g0   = (const float*)d_in[4];
    const float* be0  = (const float*)d_in[5];
    const float* Wr   = (const float*)d_in[6];
    const float* br   = (const float*)d_in[7];
    const float* gr   = (const float*)d_in[8];
    const float* ber  = (const float*)d_in[9];
    const float* Wout = (const float*)d_in[10];
    const float* bout = (const float*)d_in[11];
    const float* gW1  = (const float*)d_in[12];
    const float* gb1  = (const float*)d_in[13];
    const float* gW2  = (const float*)d_in[14];
    const float* gb2  = (const float*)d_in[15];
    const int*   nst  = (const int*)d_in[16];
    float* out = (float*)d_out;

    const int STEP_SMEM = (64 * YS) * 4 + (16 * WTS) * 4 + (64 * 16 + 64 * 6 + 64) * 4;
    cudaFuncSetAttribute(step_kernel, cudaFuncAttributeMaxDynamicSharedMemorySize, STEP_SMEM);

    init_kernel<<<Bn / 256, 256>>>(xi0);
    dim3 g0grid(Bn / 128, 2);
    gemm_h0_kernel<<<g0grid, 256>>>(h, W0, b0);
    gripper_kernel<<<Bn / 64, 256>>>(h, gW1, gb1, gW2, gb2, out);
    for (int s = 0; s < 10; s++)
        step_kernel<<<Bn / 64, 256, STEP_SMEM>>>(W0, g0, be0, Wr, br, gr, ber,
                                                 Wout, bout, nst, s);
    copy_x_kernel<<<(Bn * 16) / 256, 256>>>(out);
}

// round 4
// speedup vs baseline: 2.1820x; 1.0006x over previous
#include <cuda_runtime.h>
#include <math.h>
#include <stdint.h>

#define Bn   16384
#define HIDn 4096
#define HDn  256

// ---------------- scratch ----------------
__device__ float g_H0[Bn * HDn];   // h @ W0[:4096] + b0, computed once
__device__ float g_X[Bn * 16];     // current SE(3) state, row-major 4x4 per row

// ---------------- scalar math helpers ----------------
__device__ __forceinline__ float gelu_f(float x) {
    return 0.5f * x * (1.0f + erff(x * 0.70710678118654752f));
}
__device__ __forceinline__ float sigmoid_f(float x) {
    return 1.0f / (1.0f + expf(-x));
}
__device__ __forceinline__ uint32_t f2tf32(float x) {
    uint32_t r;
    asm("cvt.rna.tf32.f32 %0, %1;" : "=r"(r) : "f"(x));
    return r;
}
// D += A(16x8) * B(8x8), tf32 inputs, f32 accum
__device__ __forceinline__ void mma_tf32(float* c, uint32_t a0, uint32_t a1,
                                         uint32_t a2, uint32_t a3,
                                         uint32_t b0, uint32_t b1) {
    asm volatile(
        "mma.sync.aligned.m16n8k8.row.col.f32.tf32.tf32.f32 "
        "{%0,%1,%2,%3}, {%4,%5,%6,%7}, {%8,%9}, {%0,%1,%2,%3};"
        : "+f"(c[0]), "+f"(c[1]), "+f"(c[2]), "+f"(c[3])
        : "r"(a0), "r"(a1), "r"(a2), "r"(a3), "r"(b0), "r"(b1));
}

__device__ __forceinline__ void exp_se3_dev(const float* xi, float* X) {
    float wx = xi[0], wy = xi[1], wz = xi[2];
    float vx = xi[3], vy = xi[4], vz = xi[5];
    float th2 = wx * wx + wy * wy + wz * wz + 1e-20f;
    float th  = sqrtf(th2);
    bool small = th < 1e-3f;
    float ths = small ? 1.0f : th;
    float s = sinf(ths), c = cosf(ths);
    float A  = small ? (1.0f - th2 / 6.0f)            : (s / ths);
    float Bc = small ? (0.5f - th2 / 24.0f)           : ((1.0f - c) / (ths * ths));
    float Cc = small ? (1.0f / 6.0f - th2 / 120.0f)   : ((ths - s) / (ths * ths * ths));
    float wx2 = wx * wx, wy2 = wy * wy, wz2 = wz * wz;
    float xy = wx * wy, xz = wx * wz, yz = wy * wz;
    float R00 = 1.0f - Bc * (wy2 + wz2), R01 = -A * wz + Bc * xy, R02 =  A * wy + Bc * xz;
    float R10 =  A * wz + Bc * xy, R11 = 1.0f - Bc * (wx2 + wz2), R12 = -A * wx + Bc * yz;
    float R20 = -A * wy + Bc * xz, R21 =  A * wx + Bc * yz, R22 = 1.0f - Bc * (wx2 + wy2);
    float V00 = 1.0f - Cc * (wy2 + wz2), V01 = -Bc * wz + Cc * xy, V02 =  Bc * wy + Cc * xz;
    float V10 =  Bc * wz + Cc * xy, V11 = 1.0f - Cc * (wx2 + wz2), V12 = -Bc * wx + Cc * yz;
    float V20 = -Bc * wy + Cc * xz, V21 =  Bc * wx + Cc * yz, V22 = 1.0f - Cc * (wx2 + wy2);
    float tx = V00 * vx + V01 * vy + V02 * vz;
    float ty = V10 * vx + V11 * vy + V12 * vz;
    float tz = V20 * vx + V21 * vy + V22 * vz;
    X[0] = R00; X[1] = R01; X[2]  = R02; X[3]  = tx;
    X[4] = R10; X[5] = R11; X[6]  = R12; X[7]  = ty;
    X[8] = R20; X[9] = R21; X[10] = R22; X[11] = tz;
    X[12] = 0.0f; X[13] = 0.0f; X[14] = 0.0f; X[15] = 1.0f;
}

__device__ __forceinline__ void log_se3_dev(const float* X, float* xi) {
    float R00 = X[0], R01 = X[1], R02 = X[2],  px = X[3];
    float R10 = X[4], R11 = X[5], R12 = X[6],  py = X[7];
    float R20 = X[8], R21 = X[9], R22 = X[10], pz = X[11];
    float tr = R00 + R11 + R22;
    float cc = fminf(fmaxf((tr - 1.0f) * 0.5f, -1.0f + 1e-7f), 1.0f - 1e-7f);
    float th = acosf(cc);
    bool small = th < 1e-3f;
    float ths = small ? 1.0f : th;
    float sn = sinf(ths), csn = cosf(ths);
    float fac = small ? (0.5f + th * th / 12.0f) : (ths / (2.0f * sn));
    float wx = fac * (R21 - R12);
    float wy = fac * (R02 - R20);
    float wz = fac * (R10 - R01);
    float D = small ? (1.0f / 12.0f)
                    : ((1.0f - ths * sn / (2.0f * (1.0f - csn))) / (ths * ths));
    float wx2 = wx * wx, wy2 = wy * wy, wz2 = wz * wz;
    float xy = wx * wy, xz = wx * wz, yz = wy * wz;
    float V00 = 1.0f - D * (wy2 + wz2), V01 =  0.5f * wz + D * xy, V02 = -0.5f * wy + D * xz;
    float V10 = -0.5f * wz + D * xy, V11 = 1.0f - D * (wx2 + wz2), V12 =  0.5f * wx + D * yz;
    float V20 =  0.5f * wy + D * xz, V21 = -0.5f * wx + D * yz, V22 = 1.0f - D * (wx2 + wy2);
    xi[0] = wx; xi[1] = wy; xi[2] = wz;
    xi[3] = V00 * px + V01 * py + V02 * pz;
    xi[4] = V10 * px + V11 * py + V12 * pz;
    xi[5] = V20 * px + V21 * py + V22 * pz;
}

// ---------------- init: X0 = exp_se3(0.1 * xi0) ----------------
__global__ void init_kernel(const float* __restrict__ xi0) {
    int r = blockIdx.x * blockDim.x + threadIdx.x;
    if (r >= Bn) return;
    float xi[6];
#pragma unroll
    for (int j = 0; j < 6; j++) xi[j] = 0.1f * xi0[r * 6 + j];
    float X[16];
    exp_se3_dev(xi, X);
#pragma unroll
    for (int j = 0; j < 16; j++) g_X[(size_t)r * 16 + j] = X[j];
}

// ---------------- H0 = h @ W0[:4096,:] + b0, tf32 tensor cores ----------------
// block tile 128(M) x 128(N); 8 warps, warp tile 32x64; k-tile 32
#define AP 36   // As row pad (words): 144B rows -> conflict-free frags + aligned uint4
#define BP 136  // Bs row pad: 544B rows
__global__ void __launch_bounds__(256) gemm_h0_kernel(
    const float* __restrict__ h, const float* __restrict__ W0, const float* __restrict__ b0) {
    __shared__ __align__(16) uint32_t As[128 * AP];
    __shared__ __align__(16) uint32_t Bs[32 * BP];
    int brow = blockIdx.x * 128;
    int n0   = blockIdx.y * 128;
    int tid  = threadIdx.x;
    int wid  = tid >> 5, lane = tid & 31;
    int g = lane >> 2, t = lane & 3;
    int warp_m = (wid >> 1) * 32;
    int warp_n = (wid & 1) * 64;

    float acc[2][8][4];
#pragma unroll
    for (int mf = 0; mf < 2; mf++)
#pragma unroll
        for (int nf = 0; nf < 8; nf++)
#pragma unroll
            for (int q = 0; q < 4; q++) acc[mf][nf][q] = 0.0f;

    for (int k0 = 0; k0 < HIDn; k0 += 32) {
        // stage A 128x32 (pre-converted tf32)
#pragma unroll
        for (int q = 0; q < 4; q++) {
            int f = tid + q * 256;
            int row = f >> 3, c4 = (f & 7) * 4;
            float4 v = *(const float4*)(h + (size_t)(brow + row) * HIDn + k0 + c4);
            uint4 u = make_uint4(f2tf32(v.x), f2tf32(v.y), f2tf32(v.z), f2tf32(v.w));
            *(uint4*)&As[row * AP + c4] = u;
        }
        // stage B 32x128
#pragma unroll
        for (int q = 0; q < 4; q++) {
            int f = tid + q * 256;
            int row = f >> 5, c4 = (f & 31) * 4;
            float4 v = *(const float4*)(W0 + (size_t)(k0 + row) * HDn + n0 + c4);
            uint4 u = make_uint4(f2tf32(v.x), f2tf32(v.y), f2tf32(v.z), f2tf32(v.w));
            *(uint4*)&Bs[row * BP + c4] = u;
        }
        __syncthreads();
#pragma unroll
        for (int k8 = 0; k8 < 4; k8++) {
            int kb = k8 * 8;
            uint32_t a[2][4];
#pragma unroll
            for (int mf = 0; mf < 2; mf++) {
                int r0 = warp_m + mf * 16 + g;
                a[mf][0] = As[r0 * AP + kb + t];
                a[mf][1] = As[(r0 + 8) * AP + kb + t];
                a[mf][2] = As[r0 * AP + kb + t + 4];
                a[mf][3] = As[(r0 + 8) * AP + kb + t + 4];
            }
#pragma unroll
            for (int nf = 0; nf < 8; nf++) {
                int nn = warp_n + nf * 8 + g;
                uint32_t bb0 = Bs[(kb + t) * BP + nn];
                uint32_t bb1 = Bs[(kb + t + 4) * BP + nn];
                mma_tf32(acc[0][nf], a[0][0], a[0][1], a[0][2], a[0][3], bb0, bb1);
                mma_tf32(acc[1][nf], a[1][0], a[1][1], a[1][2], a[1][3], bb0, bb1);
            }
        }
        __syncthreads();
    }
    // epilogue: + b0, write g_H0
#pragma unroll
    for (int mf = 0; mf < 2; mf++) {
        int r0 = brow + warp_m + mf * 16 + g;
#pragma unroll
        for (int nf = 0; nf < 8; nf++) {
            int c0 = n0 + warp_n + nf * 8 + 2 * t;
            float bb0 = b0[c0], bb1 = b0[c0 + 1];
            *(float2*)&g_H0[(size_t)r0 * HDn + c0] =
                make_float2(acc[mf][nf][0] + bb0, acc[mf][nf][1] + bb1);
            *(float2*)&g_H0[(size_t)(r0 + 8) * HDn + c0] =
                make_float2(acc[mf][nf][2] + bb0, acc[mf][nf][3] + bb1);
        }
    }
}

// ---------------- gripper = sigmoid(gelu(h @ gW1 + gb1) @ gW2 + gb2) ----------------
__global__ void __launch_bounds__(256) gripper_kernel(
    const float* __restrict__ h, const float* __restrict__ gW1,
    const float* __restrict__ gb1, const float* __restrict__ gW2,
    const float* __restrict__ gb2, float* __restrict__ out) {
    __shared__ __align__(16) float As2[32][68];
    __shared__ __align__(16) float Bs2[32][64];
    __shared__ float sred[64][16];
    int brow = blockIdx.x * 64;
    int tid = threadIdx.x;
    int tm = tid >> 4;
    int tn = tid & 15;
    float acc[4][4];
#pragma unroll
    for (int i = 0; i < 4; i++)
#pragma unroll
        for (int j = 0; j < 4; j++) acc[i][j] = 0.0f;

    for (int k0 = 0; k0 < HIDn; k0 += 32) {
#pragma unroll
        for (int q = 0; q < 2; q++) {
            int f = tid + q * 256;
            int row = f >> 3, kc = (f & 7) * 4;
            float4 av = *(const float4*)(h + (size_t)(brow + row) * HIDn + k0 + kc);
            As2[kc + 0][row] = av.x; As2[kc + 1][row] = av.y;
            As2[kc + 2][row] = av.z; As2[kc + 3][row] = av.w;
        }
#pragma unroll
        for (int q = 0; q < 2; q++) {
            int f = tid + q * 256;
            int row = f >> 4, col = (f & 15) * 4;
            *(float4*)&Bs2[row][col] = *(const float4*)(gW1 + (size_t)(k0 + row) * 64 + col);
        }
        __syncthreads();
#pragma unroll
        for (int kk = 0; kk < 32; kk++) {
            float a[4], b[4];
            *(float4*)&a[0] = *(float4*)&As2[kk][tm * 4];
            *(float4*)&b[0] = *(float4*)&Bs2[kk][tn * 4];
#pragma unroll
            for (int i = 0; i < 4; i++)
#pragma unroll
                for (int j = 0; j < 4; j++) acc[i][j] += a[i] * b[j];
        }
        __syncthreads();
    }
#pragma unroll
    for (int i = 0; i < 4; i++) {
        float p = 0.0f;
#pragma unroll
        for (int j = 0; j < 4; j++) {
            int c = tn * 4 + j;
            p += gelu_f(acc[i][j] + gb1[c]) * gW2[c];
        }
        sred[tm * 4 + i][tn] = p;
    }
    __syncthreads();
    if (tid < 64) {
        float s = 0.0f;
#pragma unroll
        for (int t2 = 0; t2 < 16; t2++) s += sred[tid][t2];
        out[(size_t)Bn * 16 + brow + tid] = sigmoid_f(s + gb2[0]);
    }
}

// ---------------- layernorm over 256 cols (ys stride 260), 8 warps x 8 rows ----------------
#define YS 260
#define WTS 264
__device__ __forceinline__ void block_ln(float* ys, const float* __restrict__ g,
                                         const float* __restrict__ be, int wid, int lane) {
    float gv[8], bv[8];
#pragma unroll
    for (int j = 0; j < 8; j++) { gv[j] = g[lane + j * 32]; bv[j] = be[lane + j * 32]; }
#pragma unroll
    for (int rr = 0; rr < 8; rr++) {
        int r = wid * 8 + rr;
        float v[8]; float s = 0.0f, s2 = 0.0f;
#pragma unroll
        for (int j = 0; j < 8; j++) {
            v[j] = ys[r * YS + lane + j * 32];
            s += v[j]; s2 += v[j] * v[j];
        }
#pragma unroll
        for (int o = 16; o > 0; o >>= 1) {
            s  += __shfl_xor_sync(0xffffffffu, s,  o);
            s2 += __shfl_xor_sync(0xffffffffu, s2, o);
        }
        float m   = s * (1.0f / HDn);
        float var = s2 * (1.0f / HDn) - m * m;
        float rv  = rsqrtf(var + 1e-5f);
#pragma unroll
        for (int j = 0; j < 8; j++)
            ys[r * YS + lane + j * 32] = (v[j] - m) * rv * gv[j] + bv[j];
    }
}

// ---------------- one ODE step, fused, tensor-core hidden layers ----------------
// block = 64 rows, 256 threads; warp tile 32x64 (warps 2x4)
__global__ void __launch_bounds__(256) step_kernel(
    const float* __restrict__ W0,  const float* __restrict__ g0,
    const float* __restrict__ be0, const float* __restrict__ Wr,
    const float* __restrict__ br,  const float* __restrict__ gr,
    const float* __restrict__ ber, const float* __restrict__ Wout,
    const float* __restrict__ bout, const int* __restrict__ n_steps_p, int step) {
    extern __shared__ float smem_pool[];
    float*    ys   = smem_pool;                 // 64*260
    uint32_t* wt   = (uint32_t*)(ys + 64 * YS); // 16*264 (tf32)
    float*    Xs   = (float*)(wt + 16 * WTS);   // 64*16
    float*    xis  = Xs + 64 * 16;              // 64*6
    float*    temb = xis + 64 * 6;              // 64

    int ns = *n_steps_p;
    if (step >= ns) return;
    float dt = 1.0f / (float)ns;
    float tval = (float)step * dt;

    int tid = threadIdx.x;
    int brow = blockIdx.x * 64;
    int wid = tid >> 5, lane = tid & 31;
    int g = lane >> 2, t = lane & 3;

    // phase 0: temb + per-row log_se3 (threads 0..63)
    if (tid < 64) {
        int j = tid & 31;
        float freq = expf(-(float)j * (logf(10000.0f) / 31.0f));
        float e = tval * freq;
        temb[tid] = (tid < 32) ? sinf(e) : cosf(e);
        float X[16];
#pragma unroll
        for (int q = 0; q < 16; q++) {
            X[q] = g_X[(size_t)(brow + tid) * 16 + q];
            Xs[tid * 16 + q] = X[q];
        }
        float xi[6];
        log_se3_dev(X, xi);
#pragma unroll
        for (int q = 0; q < 6; q++) xis[tid * 6 + q] = xi[q];
    }
    __syncthreads();

    // phase 1: input layer; thread owns column c = tid for all 64 rows
    {
        float tc = 0.0f;
#pragma unroll 8
        for (int d = 0; d < 64; d++)
            tc += temb[d] * W0[(size_t)(4102 + d) * HDn + tid];
        float w0xi[6];
#pragma unroll
        for (int j = 0; j < 6; j++) w0xi[j] = W0[(size_t)(4096 + j) * HDn + tid];
        for (int r = 0; r < 64; r++) {
            float v = g_H0[(size_t)(brow + r) * HDn + tid] + tc;
#pragma unroll
            for (int j = 0; j < 6; j++) v += xis[r * 6 + j] * w0xi[j];
            ys[r * YS + tid] = gelu_f(v);
        }
    }
    __syncthreads();
    block_ln(ys, g0, be0, wid, lane);
    __syncthreads();

    // phase 2: 3 hidden layers via tf32 mma (64x256 @ 256x256)
    int warp_m = (wid >> 2) * 32;
    int warp_n = (wid & 3) * 64;
    for (int l = 0; l < 3; l++) {
        const float* Wl = Wr + (size_t)l * HDn * HDn;
        float acc[2][8][4];
#pragma unroll
        for (int mf = 0; mf < 2; mf++)
#pragma unroll
            for (int nf = 0; nf < 8; nf++)
#pragma unroll
                for (int q = 0; q < 4; q++) acc[mf][nf][q] = 0.0f;

        for (int k0 = 0; k0 < HDn; k0 += 16) {
            // stage 16x256 weight tile, pre-converted; thread -> column tid
#pragma unroll
            for (int i = 0; i < 16; i++)
                wt[i * WTS + tid] = f2tf32(Wl[(size_t)(k0 + i) * HDn + tid]);
            __syncthreads();
#pragma unroll
            for (int k8 = 0; k8 < 2; k8++) {
                int kb = k8 * 8;
                int kcol = k0 + kb;
                uint32_t a[2][4];
#pragma unroll
                for (int mf = 0; mf < 2; mf++) {
                    int r0 = warp_m + mf * 16 + g;
                    a[mf][0] = f2tf32(ys[r0 * YS + kcol + t]);
                    a[mf][1] = f2tf32(ys[(r0 + 8) * YS + kcol + t]);
                    a[mf][2] = f2tf32(ys[r0 * YS + kcol + t + 4]);
                    a[mf][3] = f2tf32(ys[(r0 + 8) * YS + kcol + t + 4]);
                }
#pragma unroll
                for (int nf = 0; nf < 8; nf++) {
                    int nn = warp_n + nf * 8 + g;
                    uint32_t bb0 = wt[(kb + t) * WTS + nn];
                    uint32_t bb1 = wt[(kb + t + 4) * WTS + nn];
                    mma_tf32(acc[0][nf], a[0][0], a[0][1], a[0][2], a[0][3], bb0, bb1);
                    mma_tf32(acc[1][nf], a[1][0], a[1][1], a[1][2], a[1][3], bb0, bb1);
                }
            }
            __syncthreads();
        }
        // epilogue: gelu(acc + br) back into ys, then LN
#pragma unroll
        for (int nf = 0; nf < 8; nf++) {
            int c0 = warp_n + nf * 8 + 2 * t;
            float bb0 = br[l * HDn + c0], bb1 = br[l * HDn + c0 + 1];
#pragma unroll
            for (int mf = 0; mf < 2; mf++) {
                int r0 = warp_m + mf * 16 + g;
                ys[r0 * YS + c0]           = gelu_f(acc[mf][nf][0] + bb0);
                ys[r0 * YS + c0 + 1]       = gelu_f(acc[mf][nf][1] + bb1);
                ys[(r0 + 8) * YS + c0]     = gelu_f(acc[mf][nf][2] + bb0);
                ys[(r0 + 8) * YS + c0 + 1] = gelu_f(acc[mf][nf][3] + bb1);
            }
        }
        __syncthreads();
        block_ln(ys, gr + l * HDn, ber + l * HDn, wid, lane);
        __syncthreads();
    }

    // phase 3: v = y @ Wout + bout ; X = X @ exp_se3(dt*v)
    for (int rr = 0; rr < 8; rr++) {
        int r = wid * 8 + rr;
        float p[6] = {0, 0, 0, 0, 0, 0};
        for (int c = lane; c < HDn; c += 32) {
            float yv = ys[r * YS + c];
#pragma unroll
            for (int j = 0; j < 6; j++) p[j] += yv * Wout[c * 6 + j];
        }
#pragma unroll
        for (int j = 0; j < 6; j++)
#pragma unroll
            for (int o = 16; o > 0; o >>= 1)
                p[j] += __shfl_xor_sync(0xffffffffu, p[j], o);
        if (lane == 0) {
            float xi[6];
#pragma unroll
            for (int j = 0; j < 6; j++) xi[j] = dt * (p[j] + bout[j]);
            float M[16];
            exp_se3_dev(xi, M);
            const float* Xo = &Xs[r * 16];
            float Xn[16];
#pragma unroll
            for (int i = 0; i < 4; i++)
#pragma unroll
                for (int j = 0; j < 4; j++) {
                    float s = 0.0f;
#pragma unroll
                    for (int k = 0; k < 4; k++) s += Xo[i * 4 + k] * M[k * 4 + j];
                    Xn[i * 4 + j] = s;
                }
#pragma unroll
            for (int q = 0; q < 16; q++) g_X[(size_t)(brow + r) * 16 + q] = Xn[q];
        }
    }
}

// ---------------- final copy of X into d_out ----------------
__global__ void copy_x_kernel(float* __restrict__ out) {
    int i = blockIdx.x * blockDim.x + threadIdx.x;
    if (i < Bn * 16) out[i] = g_X[i];
}

// ---------------- launch ----------------
extern "C" void kernel_launch(void* const* d_in, const int* in_sizes, int n_in,
                              void* d_out, int out_size) {
    const float* h    = (const float*)d_in[0];
    const float* xi0  = (const float*)d_in[1];
    const float* W0   = (const float*)d_in[2];
    const float* b0   = (const float*)d_in[3];
    const float* g0   = (const float*)d_in[4];
    const float* be0  = (const float*)d_in[5];
    const float* Wr   = (const float*)d_in[6];
    const float* br   = (const float*)d_in[7];
    const float* gr   = (const float*)d_in[8];
    const float* ber  = (const float*)d_in[9];
    const float* Wout = (const float*)d_in[10];
    const float* bout = (const float*)d_in[11];
    const float* gW1  = (const float*)d_in[12];
    const float* gb1  = (const float*)d_in[13];
    const float* gW2  = (const float*)d_in[14];
    const float* gb2  = (const float*)d_in[15];
    const int*   nst  = (const int*)d_in[16];
    float* out = (float*)d_out;

    const int STEP_SMEM = (64 * YS) * 4 + (16 * WTS) * 4 + (64 * 16 + 64 * 6 + 64) * 4;
    cudaFuncSetAttribute(step_kernel, cudaFuncAttributeMaxDynamicSharedMemorySize, STEP_SMEM);

    init_kernel<<<Bn / 256, 256>>>(xi0);
    dim3 g0grid(Bn / 128, 2);
    gemm_h0_kernel<<<g0grid, 256>>>(h, W0, b0);
    gripper_kernel<<<Bn / 64, 256>>>(h, gW1, gb1, gW2, gb2, out);
    for (int s = 0; s < 10; s++)
        step_kernel<<<Bn / 64, 256, STEP_SMEM>>>(W0, g0, be0, Wr, br, gr, ber,
                                                 Wout, bout, nst, s);
    copy_x_kernel<<<(Bn * 16) / 256, 256>>>(out);
}